// round 1
// baseline (speedup 1.0000x reference)
#include <cuda_runtime.h>

// ---- problem constants ----
#define Bb   32      // batch
#define Ii   32      // input capsules
#define AIN  16      // input atoms
#define OD   10      // output classes
#define OA   16      // output atoms
#define HWp  144     // 12*12 spatial
#define Kk   160     // OD*OA
#define NPOS (Bb*HWp)   // 4608 positions

// votes scratch: [pos][i][a_out*OD + d]  (note: (a,d) order for conflict-free routing)
__device__ float g_votes[NPOS * Ii * Kk];   // 23,592,960 floats = 94.4 MB

// ============================================================================
// Kernel A: votes[b,i,d,a,hw] = sum_ain x[b,i,ain,hw] * w[i,ain,d*16+a]
// One block per (b,i) pair. 160 threads, thread t -> (d = t%10, a = t/10),
// stored at offset a*10+d == t (so stores are fully coalesced and kernel B's
// preferred layout falls out for free).
// ============================================================================
__global__ void __launch_bounds__(160) votes_kernel(const float* __restrict__ x,
                                                    const float* __restrict__ w)
{
    const int bi = blockIdx.x;        // b*32 + i
    const int b  = bi >> 5;
    const int i  = bi & 31;
    const int t  = threadIdx.x;       // 0..159
    const int d  = t % OD;
    const int a  = t / OD;
    const int kcol = d * OA + a;      // torch k index

    __shared__ float xs[AIN * HWp];   // 9 KB

    // load x[b,i,:,:] (contiguous 2304 floats)
    const float* xg = x + bi * (AIN * HWp);
    for (int idx = t; idx < AIN * HWp; idx += 160) xs[idx] = xg[idx];

    // weight column -> registers (16 scattered LDG, L1/L2 hits after warm-up)
    float wr[AIN];
#pragma unroll
    for (int ai = 0; ai < AIN; ai++)
        wr[ai] = w[(i * AIN + ai) * Kk + kcol];

    __syncthreads();

    const int stride = Ii * Kk;                       // 5120
    float* vbase = g_votes + (b * HWp) * stride + i * Kk + t;

#pragma unroll 4
    for (int h4 = 0; h4 < HWp / 4; h4++) {
        float4 acc = make_float4(0.f, 0.f, 0.f, 0.f);
#pragma unroll
        for (int ai = 0; ai < AIN; ai++) {
            // broadcast float4 from smem: 1 LDS.128 per 4 FFMA per a
            float4 xv = *(const float4*)(xs + ai * HWp + h4 * 4);
            acc.x = fmaf(wr[ai], xv.x, acc.x);
            acc.y = fmaf(wr[ai], xv.y, acc.y);
            acc.z = fmaf(wr[ai], xv.z, acc.z);
            acc.w = fmaf(wr[ai], xv.w, acc.w);
        }
        float* p = vbase + (h4 * 4) * stride;
        p[0]          = acc.x;    // warp writes 128B contiguous per store
        p[stride]     = acc.y;
        p[2 * stride] = acc.z;
        p[3 * stride] = acc.w;
    }
}

// ============================================================================
// Kernel B: dynamic routing, one block per spatial position (b,hw).
// 320 threads: t = i*10+d for logit-space ops; t<160 = a*10+d for (d,a) ops.
// Entire [32,10,16] votes slice lives in SMEM; 3 iterations, no global
// intermediates.
// ============================================================================
__global__ void __launch_bounds__(320) route_kernel(const float* __restrict__ bias,
                                                    float* __restrict__ out)
{
    const int pos = blockIdx.x;       // b*144 + hw
    const int t   = threadIdx.x;      // 0..319

    __shared__ float vs[Ii * Kk];     // 20 KB votes slice, layout [i][a*10+d]
    __shared__ float logits[Ii * OD]; // 320
    __shared__ float route[Ii * OD];  // 320
    __shared__ float act[Kk];         // 160, layout [a*10+d]
    __shared__ float sq[Kk];
    __shared__ float scale_s[OD];
    __shared__ float bs[Kk];          // bias, layout [a*10+d]

    // load votes slice: 5120 contiguous floats via float4
    {
        const float4* vg  = (const float4*)(g_votes + pos * (Ii * Kk));
        float4*       vsm = (float4*)vs;
        for (int idx = t; idx < (Ii * Kk) / 4; idx += 320) vsm[idx] = vg[idx];
    }
    const int dd = t % OD;            // class  (valid as (d,a) map for t<160)
    const int aa = t / OD;            // atom
    if (t < Kk) bs[t] = bias[dd * OA + aa];
    logits[t] = 0.f;
    __syncthreads();

    const int li = t / OD;            // input capsule for (i,d) ops
    const int ld = t % OD;            // class for (i,d) ops

    float av = 0.f;                   // this thread's activation (t<160)

    for (int r = 0; r < 3; r++) {
        // ---- softmax over d (logits all zero on r==0 -> uniform 0.1) ----
        float rt;
        if (r == 0) {
            rt = 0.1f;
        } else {
            float m = logits[li * OD];
#pragma unroll
            for (int d2 = 1; d2 < OD; d2++) m = fmaxf(m, logits[li * OD + d2]);
            float s = 0.f;
#pragma unroll
            for (int d2 = 0; d2 < OD; d2++) s += __expf(logits[li * OD + d2] - m);
            rt = __expf(logits[t] - m) / s;
        }
        route[t] = rt;
        __syncthreads();

        // ---- preact[d][a] = bias + sum_i route[i][d] * v[i][d][a] ----
        if (t < Kk) {
            float acc = bs[t];
#pragma unroll 8
            for (int ii = 0; ii < Ii; ii++)          // vs read: conflict-free
                acc = fmaf(route[ii * OD + dd], vs[ii * Kk + t], acc);
            sq[t] = acc * acc;
            av = acc;                                // pre-squash value
        }
        __syncthreads();

        // ---- squash norm over atoms (16 values per class) ----
        if (t < OD) {
            float n2 = 0.f;
#pragma unroll
            for (int a2 = 0; a2 < OA; a2++) n2 += sq[a2 * OD + t];
            scale_s[t] = sqrtf(n2) / (1.f + n2);
        }
        __syncthreads();

        if (t < Kk) {
            av *= scale_s[dd];
            act[t] = av;
        }

        // ---- agreement: logits[i][d] += sum_a v[i][d][a] * act[d][a] ----
        if (r < 2) {
            __syncthreads();                         // act visible to all
            float s2 = 0.f;
            const float* vrow = vs + li * Kk + ld;   // stride-10 reads: multicast
#pragma unroll
            for (int a2 = 0; a2 < OA; a2++)
                s2 = fmaf(vrow[a2 * OD], act[a2 * OD + ld], s2);
            logits[t] += s2;
            __syncthreads();
        }
    }

    // ---- output: out[b][d][a][hw] ----
    if (t < Kk) {
        const int b  = pos / HWp;
        const int hw = pos % HWp;
        out[((b * OD + dd) * OA + aa) * HWp + hw] = av;
    }
}

extern "C" void kernel_launch(void* const* d_in, const int* in_sizes, int n_in,
                              void* d_out, int out_size)
{
    const float* x    = (const float*)d_in[0];   // [32,32,16,12,12]
    const float* w    = (const float*)d_in[1];   // [32,16,160]
    const float* bias = (const float*)d_in[2];   // [10,16,1,1]
    float* out = (float*)d_out;                  // [32,10,16,12,12]

    votes_kernel<<<Bb * Ii, 160>>>(x, w);
    route_kernel<<<NPOS, 320>>>(bias, out);
}

// round 4
// speedup vs baseline: 1.0028x; 1.0028x over previous
#include <cuda_runtime.h>

// ---- problem constants ----
#define Bb   32      // batch
#define Ii   32      // input capsules
#define AIN  16      // input atoms
#define OD   10      // output classes
#define OA   16      // output atoms
#define HWp  144     // 12*12 spatial
#define Kk   160     // OD*OA
#define NPOS (Bb*HWp)   // 4608 positions

// votes scratch, layout [pos][d][i][a]:
//   route_kernel thread (warp=d, lane=i) reads 16 consecutive floats;
//   a warp reads one contiguous 2KB chunk.
__device__ float g_votes[(size_t)NPOS * Ii * Kk];   // 94.4 MB

// ============================================================================
// Kernel A: votes[b,i,d,a,hw] = sum_ain x[b,i,ain,hw] * w[i,ain,d*16+a]
// One block per (b,i). 160 threads, t = d*16+a (== weight column index).
// Plain scalar FFMA inner loop (no arch-gated PTX).
// ============================================================================
__global__ void __launch_bounds__(160) votes_kernel(const float* __restrict__ x,
                                                    const float* __restrict__ w)
{
    const int bi = blockIdx.x;        // b*32 + i
    const int b  = bi >> 5;
    const int i  = bi & 31;
    const int t  = threadIdx.x;       // 0..159 == d*16+a
    const int d  = t >> 4;
    const int a  = t & 15;

    __shared__ __align__(16) float xs[AIN * HWp];   // 9 KB

    // load x[b,i,:,:] (contiguous 2304 floats)
    const float* xg = x + (size_t)bi * (AIN * HWp);
    for (int idx = t; idx < AIN * HWp; idx += 160) xs[idx] = xg[idx];

    // weight column -> registers (coalesced: consecutive t -> consecutive addr)
    float wr[AIN];
#pragma unroll
    for (int ai = 0; ai < AIN; ai++)
        wr[ai] = w[(i * AIN + ai) * Kk + t];

    __syncthreads();

    float* vbase = g_votes + (size_t)(b * HWp) * (Ii * Kk)
                 + (size_t)(d * (Ii * OA) + i * OA + a);

#pragma unroll 4
    for (int h4 = 0; h4 < HWp / 4; h4++) {
        float4 acc = make_float4(0.f, 0.f, 0.f, 0.f);
#pragma unroll
        for (int ai = 0; ai < AIN; ai++) {
            // one LDS.128 broadcast feeds 4 FFMA
            float4 xv = *(const float4*)(xs + ai * HWp + h4 * 4);
            acc.x = fmaf(wr[ai], xv.x, acc.x);
            acc.y = fmaf(wr[ai], xv.y, acc.y);
            acc.z = fmaf(wr[ai], xv.z, acc.z);
            acc.w = fmaf(wr[ai], xv.w, acc.w);
        }
        float* p = vbase + (size_t)(h4 * 4) * (Ii * Kk);
        p[0]               = acc.x;   // warp writes 128B contiguous per store
        p[Ii * Kk]         = acc.y;
        p[2 * (Ii * Kk)]   = acc.z;
        p[3 * (Ii * Kk)]   = acc.w;
    }
}

// ============================================================================
// Kernel B: dynamic routing, one block per spatial position (b,hw).
// 320 threads = 10 warps. warp = output class d, lane = input capsule i.
// Each thread holds votes v[i,d,0..15] in registers; preact reduction over i
// is a warp butterfly all-reduce; squash + agreement are register-only.
// SMEM: only a 2x10x32 exp-exchange array (softmax over d crosses warps).
// Exactly 2 __syncthreads() in the whole kernel.
// ============================================================================
__global__ void __launch_bounds__(320) route_kernel(const float* __restrict__ bias,
                                                    float* __restrict__ out)
{
    const int pos  = blockIdx.x;            // b*144 + hw
    const int d    = threadIdx.x >> 5;      // warp id = class
    const int lane = threadIdx.x & 31;      // = input capsule i

    __shared__ float ex[2][OD][32];         // exp(logits) exchange, double-buffered

    // ---- votes for (i=lane, d): 16 consecutive floats -> 4 x LDG.128 ----
    float va[OA];
    {
        const float4* vg = (const float4*)(g_votes + (size_t)pos * (Ii * Kk)
                                           + d * (Ii * OA) + lane * OA);
        float4 q0 = vg[0], q1 = vg[1], q2 = vg[2], q3 = vg[3];
        va[0]=q0.x; va[1]=q0.y; va[2]=q0.z;  va[3]=q0.w;
        va[4]=q1.x; va[5]=q1.y; va[6]=q1.z;  va[7]=q1.w;
        va[8]=q2.x; va[9]=q2.y; va[10]=q2.z; va[11]=q2.w;
        va[12]=q3.x; va[13]=q3.y; va[14]=q3.z; va[15]=q3.w;
    }

    // ---- bias[d][0..15] (broadcast loads, L1-resident) ----
    float bs[OA];
    {
        const float4* bg = (const float4*)(bias + d * OA);
        float4 q0 = bg[0], q1 = bg[1], q2 = bg[2], q3 = bg[3];
        bs[0]=q0.x; bs[1]=q0.y; bs[2]=q0.z;  bs[3]=q0.w;
        bs[4]=q1.x; bs[5]=q1.y; bs[6]=q1.z;  bs[7]=q1.w;
        bs[8]=q2.x; bs[9]=q2.y; bs[10]=q2.z; bs[11]=q2.w;
        bs[12]=q3.x; bs[13]=q3.y; bs[14]=q3.z; bs[15]=q3.w;
    }

    float logit = 0.f;
    float act[OA];
    float scale = 0.f;

#pragma unroll
    for (int r = 0; r < 3; r++) {
        // ---- softmax over d (cross-warp via smem exp exchange) ----
        float route;
        if (r == 0) {
            route = 0.1f;                   // softmax of zeros
        } else {
            // |logit| is small here, so max-subtraction is safely skipped
            float e = __expf(logit);
            ex[r & 1][d][lane] = e;
            __syncthreads();
            float s = 0.f;
#pragma unroll
            for (int d2 = 0; d2 < OD; d2++) s += ex[r & 1][d2][lane];
            route = __fdividef(e, s);
        }

        // ---- preact[d][a] = bias + sum_i route_i * v[i][d][a] ----
        // butterfly all-reduce over the 32 lanes (i) of this warp
        float n2 = 0.f;
#pragma unroll
        for (int a = 0; a < OA; a++) {
            float p = route * va[a];
#pragma unroll
            for (int off = 16; off; off >>= 1)
                p += __shfl_xor_sync(0xffffffffu, p, off);
            p += bs[a];
            act[a] = p;                     // pre-squash value (all lanes hold it)
            n2 = fmaf(p, p, n2);
        }

        // ---- squash scale = |v|/(1+|v|^2), register-only ----
        scale = __fdividef(sqrtf(n2), 1.f + n2);

        if (r < 2) {
            // ---- agreement: logits[i][d] += sum_a v[i][d][a] * act[d][a] ----
            float s2 = 0.f;
#pragma unroll
            for (int a = 0; a < OA; a++) s2 = fmaf(va[a], act[a], s2);
            logit += s2 * scale;            // act_true = act_pre * scale
        }
    }

    // ---- output: out[b][d][a][hw], lane a<16 writes atom a ----
    if (lane < OA) {
        float ov = act[0];
#pragma unroll
        for (int a = 1; a < OA; a++) if (lane == a) ov = act[a];
        ov *= scale;
        const int b  = pos / HWp;
        const int hw = pos - b * HWp;
        out[((size_t)(b * OD + d) * OA + lane) * HWp + hw] = ov;
    }
}

extern "C" void kernel_launch(void* const* d_in, const int* in_sizes, int n_in,
                              void* d_out, int out_size)
{
    const float* x    = (const float*)d_in[0];   // [32,32,16,12,12]
    const float* w    = (const float*)d_in[1];   // [32,16,160]
    const float* bias = (const float*)d_in[2];   // [10,16,1,1]
    float* out = (float*)d_out;                  // [32,10,16,12,12]

    votes_kernel<<<Bb * Ii, 160>>>(x, w);
    route_kernel<<<NPOS, 320>>>(bias, out);
}

// round 6
// speedup vs baseline: 1.1938x; 1.1905x over previous
#include <cuda_runtime.h>

// ---- problem constants ----
#define Bb   32      // batch
#define Ii   32      // input capsules
#define AIN  16      // input atoms
#define OD   10      // output classes
#define OA   16      // output atoms
#define HWp  144     // 12*12 spatial
#define Kk   160     // OD*OA
#define NPOS (Bb*HWp)   // 4608 positions

// votes scratch, layout [pos][d][i][a]
__device__ float g_votes[(size_t)NPOS * Ii * Kk];   // 94.4 MB

// ============================================================================
// Kernel A: votes[b,i,d,a,hw] = sum_ain x[b,i,ain,hw] * w[i,ain,d*16+a]
// One block per (b,i). 160 threads, t = d*16+a. Scalar FFMA.
// ============================================================================
__global__ void __launch_bounds__(160) votes_kernel(const float* __restrict__ x,
                                                    const float* __restrict__ w)
{
    const int bi = blockIdx.x;        // b*32 + i
    const int b  = bi >> 5;
    const int i  = bi & 31;
    const int t  = threadIdx.x;       // 0..159 == d*16+a
    const int d  = t >> 4;
    const int a  = t & 15;

    __shared__ __align__(16) float xs[AIN * HWp];   // 9 KB

    const float* xg = x + (size_t)bi * (AIN * HWp);
    for (int idx = t; idx < AIN * HWp; idx += 160) xs[idx] = xg[idx];

    float wr[AIN];
#pragma unroll
    for (int ai = 0; ai < AIN; ai++)
        wr[ai] = w[(i * AIN + ai) * Kk + t];

    __syncthreads();

    float* vbase = g_votes + (size_t)(b * HWp) * (Ii * Kk)
                 + (size_t)(d * (Ii * OA) + i * OA + a);

#pragma unroll 4
    for (int h4 = 0; h4 < HWp / 4; h4++) {
        float4 acc = make_float4(0.f, 0.f, 0.f, 0.f);
#pragma unroll
        for (int ai = 0; ai < AIN; ai++) {
            float4 xv = *(const float4*)(xs + ai * HWp + h4 * 4);
            acc.x = fmaf(wr[ai], xv.x, acc.x);
            acc.y = fmaf(wr[ai], xv.y, acc.y);
            acc.z = fmaf(wr[ai], xv.z, acc.z);
            acc.w = fmaf(wr[ai], xv.w, acc.w);
        }
        float* p = vbase + (size_t)(h4 * 4) * (Ii * Kk);
        p[0]               = acc.x;
        p[Ii * Kk]         = acc.y;
        p[2 * (Ii * Kk)]   = acc.z;
        p[3 * (Ii * Kk)]   = acc.w;
    }
}

// ============================================================================
// Kernel B: routing. One block per position, 10 warps (warp = class d).
// lane = (i16 = lane&15 -> capsules 2*i16, 2*i16+1 ; grp = lane>>4 -> atom
// half). 51 shuffles/thread total (vs 240 in the full-butterfly version).
// ============================================================================
__global__ void __launch_bounds__(320) route_kernel(const float* __restrict__ bias,
                                                    float* __restrict__ out)
{
    const int pos  = blockIdx.x;            // b*144 + hw
    const int d    = threadIdx.x >> 5;      // warp id = class
    const int lane = threadIdx.x & 31;
    const int i16  = lane & 15;             // capsule pair index
    const int grp  = lane >> 4;             // atom group: 0 -> atoms 0-7, 1 -> 8-15

    __shared__ float2 ex2[2][OD][16];       // exp(logit) pairs, per softmax round

    // votes: va0 = v[2*i16][grp*8..+8], va1 = v[2*i16+1][grp*8..+8]
    const float* vp = g_votes + (size_t)pos * (Ii * Kk)
                    + d * (Ii * OA) + (i16 * 2) * OA + grp * 8;
    float va0[8], va1[8];
    *(float4*)(va0)     = *(const float4*)(vp);
    *(float4*)(va0 + 4) = *(const float4*)(vp + 4);
    *(float4*)(va1)     = *(const float4*)(vp + OA);
    *(float4*)(va1 + 4) = *(const float4*)(vp + OA + 4);

    const int atom = grp * 8 + ((lane >> 1) & 7);   // atom this lane owns post-reduce
    const float bv = bias[d * OA + atom];

    float logitA = 0.f, logitB = 0.f;
    float outP = 0.f, outScale = 0.f;
    const unsigned FULL = 0xffffffffu;

#pragma unroll
    for (int r = 0; r < 3; r++) {
        // ---- softmax over d ----
        float routeA, routeB;
        if (r == 0) {
            routeA = routeB = 0.1f;
        } else {
            float e0 = __expf(logitA), e1 = __expf(logitB);
            if (grp == 0) ex2[r - 1][d][i16] = make_float2(e0, e1);
            __syncthreads();
            float sA = 0.f, sB = 0.f;
#pragma unroll
            for (int d2 = 0; d2 < OD; d2++) {
                float2 v = ex2[r - 1][d2][i16];
                sA += v.x; sB += v.y;
            }
            routeA = __fdividef(e0, sA);
            routeB = __fdividef(e1, sB);
        }

        // ---- p[k] = routeA*va0[k] + routeB*va1[k]  (8 own-group atoms) ----
        float q[8];
#pragma unroll
        for (int k = 0; k < 8; k++)
            q[k] = fmaf(routeB, va1[k], routeA * va0[k]);

        // ---- reduce over the 16-lane half, splitting atoms each step ----
        // off=8 (bit3): 8 atoms -> 4
        {
            const bool hi = (lane & 8) != 0;
#pragma unroll
            for (int k = 0; k < 4; k++) {
                float snd  = hi ? q[k] : q[k + 4];
                float rcv  = __shfl_xor_sync(FULL, snd, 8);
                q[k] = (hi ? q[k + 4] : q[k]) + rcv;
            }
        }
        // off=4 (bit2): 4 -> 2
        {
            const bool hi = (lane & 4) != 0;
#pragma unroll
            for (int k = 0; k < 2; k++) {
                float snd = hi ? q[k] : q[k + 2];
                float rcv = __shfl_xor_sync(FULL, snd, 4);
                q[k] = (hi ? q[k + 2] : q[k]) + rcv;
            }
        }
        // off=2 (bit1): 2 -> 1
        float s;
        {
            const bool hi = (lane & 2) != 0;
            float snd = hi ? q[0] : q[1];
            float rcv = __shfl_xor_sync(FULL, snd, 2);
            s = (hi ? q[1] : q[0]) + rcv;
        }
        // off=1: final pair sum (no split)
        s += __shfl_xor_sync(FULL, s, 1);

        const float P = s + bv;             // pre-squash preact for `atom`

        if (r < 2) {
            // ---- broadcast own-group pre-squash atoms (8 shuffles) ----
            float act[8];
#pragma unroll
            for (int k = 0; k < 8; k++)
                act[k] = __shfl_sync(FULL, P, (lane & 16) | (k << 1));

            // ---- n2 = |preact|^2 (partial + cross-group exchange) ----
            float n2p = 0.f;
#pragma unroll
            for (int k = 0; k < 8; k++) n2p = fmaf(act[k], act[k], n2p);
            float n2 = n2p + __shfl_xor_sync(FULL, n2p, 16);
            float scale = __fdividef(sqrtf(n2), 1.f + n2);

            // ---- agreement dots for the lane's two capsules ----
            float dA = 0.f, dB = 0.f;
#pragma unroll
            for (int k = 0; k < 8; k++) {
                dA = fmaf(va0[k], act[k], dA);
                dB = fmaf(va1[k], act[k], dB);
            }
            dA += __shfl_xor_sync(FULL, dA, 16);
            dB += __shfl_xor_sync(FULL, dB, 16);
            logitA = fmaf(dA, scale, logitA);
            logitB = fmaf(dB, scale, logitB);
        } else {
            // ---- final iter: norm via square-butterfly, no broadcast ----
            float sq = P * P;
#pragma unroll
            for (int off = 16; off; off >>= 1)
                sq += __shfl_xor_sync(FULL, sq, off);
            float n2 = 0.5f * sq;           // each atom counted twice
            outScale = __fdividef(sqrtf(n2), 1.f + n2);
            outP = P;
        }
    }

    // ---- output: even lane of each atom pair writes ----
    if ((lane & 1) == 0) {
        const int b  = pos / HWp;
        const int hw = pos - b * HWp;
        out[((size_t)(b * OD + d) * OA + atom) * HWp + hw] = outP * outScale;
    }
}

extern "C" void kernel_launch(void* const* d_in, const int* in_sizes, int n_in,
                              void* d_out, int out_size)
{
    const float* x    = (const float*)d_in[0];   // [32,32,16,12,12]
    const float* w    = (const float*)d_in[1];   // [32,16,160]
    const float* bias = (const float*)d_in[2];   // [10,16,1,1]
    float* out = (float*)d_out;                  // [32,10,16,12,12]

    votes_kernel<<<Bb * Ii, 160>>>(x, w);
    route_kernel<<<NPOS, 320>>>(bias, out);
}

// round 7
// speedup vs baseline: 1.5180x; 1.2715x over previous
#include <cuda_runtime.h>
#include <cuda_fp16.h>

// ---- problem constants ----
#define Bb   32      // batch
#define Ii   32      // input capsules
#define AIN  16      // input atoms
#define OD   10      // output classes
#define OA   16      // output atoms
#define HWp  144     // 12*12 spatial
#define Kk   160     // OD*OA
#define NPOS (Bb*HWp)   // 4608 positions

// votes scratch in fp16, layout [pos][d][i][a]  (47.2 MB)
__device__ __half g_votesh[(size_t)NPOS * Ii * Kk];

// ============================================================================
// Kernel A: votes[b,i,d,a,hw] = sum_ain x[b,i,ain,hw] * w[i,ain,d*16+a]
// One block per (b,i). 160 threads, t = d*16+a. fp32 FFMA, fp16 stores.
// ============================================================================
__global__ void __launch_bounds__(160) votes_kernel(const float* __restrict__ x,
                                                    const float* __restrict__ w)
{
    const int bi = blockIdx.x;        // b*32 + i
    const int b  = bi >> 5;
    const int i  = bi & 31;
    const int t  = threadIdx.x;       // 0..159 == d*16+a
    const int d  = t >> 4;
    const int a  = t & 15;

    __shared__ __align__(16) float xs[AIN * HWp];   // 9 KB

    const float* xg = x + (size_t)bi * (AIN * HWp);
    for (int idx = t; idx < AIN * HWp; idx += 160) xs[idx] = xg[idx];

    float wr[AIN];
#pragma unroll
    for (int ai = 0; ai < AIN; ai++)
        wr[ai] = w[(i * AIN + ai) * Kk + t];

    __syncthreads();

    __half* vbase = g_votesh + (size_t)(b * HWp) * (Ii * Kk)
                  + (size_t)(d * (Ii * OA) + i * OA + a);

#pragma unroll 4
    for (int h4 = 0; h4 < HWp / 4; h4++) {
        float4 acc = make_float4(0.f, 0.f, 0.f, 0.f);
#pragma unroll
        for (int ai = 0; ai < AIN; ai++) {
            float4 xv = *(const float4*)(xs + ai * HWp + h4 * 4);
            acc.x = fmaf(wr[ai], xv.x, acc.x);
            acc.y = fmaf(wr[ai], xv.y, acc.y);
            acc.z = fmaf(wr[ai], xv.z, acc.z);
            acc.w = fmaf(wr[ai], xv.w, acc.w);
        }
        __half* p = vbase + (size_t)(h4 * 4) * (Ii * Kk);
        p[0]               = __float2half_rn(acc.x);
        p[Ii * Kk]         = __float2half_rn(acc.y);
        p[2 * (Ii * Kk)]   = __float2half_rn(acc.z);
        p[3 * (Ii * Kk)]   = __float2half_rn(acc.w);
    }
}

// ============================================================================
// Kernel B: routing. One block per 2 positions, 10 warps (warp = class d).
// lane = (i16 = lane&15 -> capsules 2*i16, 2*i16+1 ; grp = lane>>4 -> atom
// half). All 4 vote loads (2 positions) issued up front for MLP; positions
// routed sequentially to cap register pressure.
// ============================================================================
__global__ void __launch_bounds__(320) route_kernel(const float* __restrict__ bias,
                                                    float* __restrict__ out)
{
    const int pos0 = blockIdx.x * 2;        // even; pos0, pos0+1 share batch b
    const int d    = threadIdx.x >> 5;      // warp id = class
    const int lane = threadIdx.x & 31;
    const int i16  = lane & 15;             // capsule pair index
    const int grp  = lane >> 4;             // atom group: 0 -> atoms 0-7, 1 -> 8-15

    __shared__ float2 ex2[2][OD][16];       // exp(logit) pairs per softmax round

    // ---- issue all 4 vote loads (2 capsules x 2 positions) up front ----
    const __half* vb = g_votesh + (size_t)pos0 * (Ii * Kk)
                     + d * (Ii * OA) + (i16 * 2) * OA + grp * 8;
    uint4 raw[4];
    raw[0] = *(const uint4*)(vb);                   // pos0, capsule 2*i16
    raw[1] = *(const uint4*)(vb + OA);              // pos0, capsule 2*i16+1
    raw[2] = *(const uint4*)(vb + Ii * Kk);         // pos1, capsule 2*i16
    raw[3] = *(const uint4*)(vb + Ii * Kk + OA);    // pos1, capsule 2*i16+1

    const int atom = grp * 8 + ((lane >> 1) & 7);   // atom this lane owns post-reduce
    const float bv = bias[d * OA + atom];
    const int b   = pos0 / HWp;
    const int hw0 = pos0 - b * HWp;
    const unsigned FULL = 0xffffffffu;

#pragma unroll
    for (int p = 0; p < 2; p++) {
        // ---- convert this position's votes to fp32 ----
        float va0[8], va1[8];
        {
            const __half2* h0 = (const __half2*)&raw[2 * p];
            const __half2* h1 = (const __half2*)&raw[2 * p + 1];
#pragma unroll
            for (int k = 0; k < 4; k++) {
                float2 f0 = __half22float2(h0[k]);
                float2 f1 = __half22float2(h1[k]);
                va0[2 * k] = f0.x; va0[2 * k + 1] = f0.y;
                va1[2 * k] = f1.x; va1[2 * k + 1] = f1.y;
            }
        }

        float logitA = 0.f, logitB = 0.f;
        float outP = 0.f, outScale = 0.f;

#pragma unroll
        for (int r = 0; r < 3; r++) {
            // ---- softmax over d ----
            float routeA, routeB;
            if (r == 0) {
                routeA = routeB = 0.1f;
            } else {
                float e0 = __expf(logitA), e1 = __expf(logitB);
                if (grp == 0) ex2[r - 1][d][i16] = make_float2(e0, e1);
                __syncthreads();
                float sA = 0.f, sB = 0.f;
#pragma unroll
                for (int d2 = 0; d2 < OD; d2++) {
                    float2 v = ex2[r - 1][d2][i16];
                    sA += v.x; sB += v.y;
                }
                routeA = __fdividef(e0, sA);
                routeB = __fdividef(e1, sB);
            }

            // ---- q[k] = routeA*va0[k] + routeB*va1[k] (8 own-group atoms) ----
            float q[8];
#pragma unroll
            for (int k = 0; k < 8; k++)
                q[k] = fmaf(routeB, va1[k], routeA * va0[k]);

            // ---- reduce over 16-lane half, splitting atoms each step ----
            {
                const bool hi = (lane & 8) != 0;
#pragma unroll
                for (int k = 0; k < 4; k++) {
                    float snd = hi ? q[k] : q[k + 4];
                    float rcv = __shfl_xor_sync(FULL, snd, 8);
                    q[k] = (hi ? q[k + 4] : q[k]) + rcv;
                }
            }
            {
                const bool hi = (lane & 4) != 0;
#pragma unroll
                for (int k = 0; k < 2; k++) {
                    float snd = hi ? q[k] : q[k + 2];
                    float rcv = __shfl_xor_sync(FULL, snd, 4);
                    q[k] = (hi ? q[k + 2] : q[k]) + rcv;
                }
            }
            float s;
            {
                const bool hi = (lane & 2) != 0;
                float snd = hi ? q[0] : q[1];
                float rcv = __shfl_xor_sync(FULL, snd, 2);
                s = (hi ? q[1] : q[0]) + rcv;
            }
            s += __shfl_xor_sync(FULL, s, 1);

            const float P = s + bv;         // pre-squash preact for `atom`

            if (r < 2) {
                // ---- broadcast own-group pre-squash atoms ----
                float act[8];
#pragma unroll
                for (int k = 0; k < 8; k++)
                    act[k] = __shfl_sync(FULL, P, (lane & 16) | (k << 1));

                float n2p = 0.f;
#pragma unroll
                for (int k = 0; k < 8; k++) n2p = fmaf(act[k], act[k], n2p);
                float n2 = n2p + __shfl_xor_sync(FULL, n2p, 16);
                float scale = __fdividef(sqrtf(n2), 1.f + n2);

                float dA = 0.f, dB = 0.f;
#pragma unroll
                for (int k = 0; k < 8; k++) {
                    dA = fmaf(va0[k], act[k], dA);
                    dB = fmaf(va1[k], act[k], dB);
                }
                dA += __shfl_xor_sync(FULL, dA, 16);
                dB += __shfl_xor_sync(FULL, dB, 16);
                logitA = fmaf(dA, scale, logitA);
                logitB = fmaf(dB, scale, logitB);
            } else {
                float sq = P * P;
#pragma unroll
                for (int off = 16; off; off >>= 1)
                    sq += __shfl_xor_sync(FULL, sq, off);
                float n2 = 0.5f * sq;       // each atom counted twice
                outScale = __fdividef(sqrtf(n2), 1.f + n2);
                outP = P;
            }
        }

        // ---- output: even lane of each atom pair writes ----
        if ((lane & 1) == 0) {
            out[((size_t)(b * OD + d) * OA + atom) * HWp + hw0 + p] = outP * outScale;
        }
    }
}

extern "C" void kernel_launch(void* const* d_in, const int* in_sizes, int n_in,
                              void* d_out, int out_size)
{
    const float* x    = (const float*)d_in[0];   // [32,32,16,12,12]
    const float* w    = (const float*)d_in[1];   // [32,16,160]
    const float* bias = (const float*)d_in[2];   // [10,16,1,1]
    float* out = (float*)d_out;                  // [32,10,16,12,12]

    votes_kernel<<<Bb * Ii, 160>>>(x, w);
    route_kernel<<<NPOS / 2, 320>>>(bias, out);
}